// round 10
// baseline (speedup 1.0000x reference)
#include <cuda_runtime.h>
#include <cuda_fp16.h>
#include <math.h>
#include <stdint.h>

#define BB 64
#define TT 2048
#define DD 512
#define UU 512

// ---------------- device scratch ----------------
__device__ float g_comb[BB * UU];
__device__ float g_scores[BB * TT];
__device__ float g_spart[2 * BB * TT];
__device__ float g_stats[BB * 2];
__device__ float g_partial[BB * 64 * DD];
__device__ __align__(16) __half g_a16[(size_t)BB * TT * DD];   // [b][t][k] fp16
__device__ __align__(16) __half g_w1t[UU * DD];                // [u][k] fp16

// ---------------- helpers ----------------
__device__ __forceinline__ uint32_t smem_u32(const void* p) {
    uint32_t a;
    asm("{ .reg .u64 t; cvta.to.shared.u64 t, %1; cvt.u32.u64 %0, t; }" : "=r"(a) : "l"(p));
    return a;
}
__device__ __forceinline__ void cpa16(uint32_t dst, const void* src) {
    asm volatile("cp.async.cg.shared.global [%0], [%1], 16;" :: "r"(dst), "l"(src) : "memory");
}
#define CP_COMMIT() asm volatile("cp.async.commit_group;" ::: "memory")
#define CP_WAIT(n)  asm volatile("cp.async.wait_group %0;" :: "n"(n) : "memory")

#define LDSM4(r, addr) \
    asm volatile("ldmatrix.sync.aligned.m8n8.x4.shared.b16 {%0,%1,%2,%3}, [%4];" \
        : "=r"((r)[0]), "=r"((r)[1]), "=r"((r)[2]), "=r"((r)[3]) : "r"(addr))

__device__ __forceinline__ uint32_t pack_h2(float x, float y) {
    __half2 h = __floats2half2_rn(x, y);
    return *(uint32_t*)&h;
}

__device__ __forceinline__ void mma_f16(float* d, const uint32_t* a, uint32_t b0, uint32_t b1) {
    asm volatile(
        "mma.sync.aligned.m16n8k16.row.col.f32.f16.f16.f32 "
        "{%0,%1,%2,%3}, {%4,%5,%6,%7}, {%8,%9}, {%0,%1,%2,%3};"
        : "+f"(d[0]), "+f"(d[1]), "+f"(d[2]), "+f"(d[3])
        : "r"(a[0]), "r"(a[1]), "r"(a[2]), "r"(a[3]), "r"(b0), "r"(b1));
}

// ---------------- prep: features fp32 -> fp16 plain [b][t][k] ----------------
__global__ void prep_a16_kernel(const float* __restrict__ feat) {
    size_t i = ((size_t)blockIdx.x * 256 + threadIdx.x) * 4;
    float4 fv = *(const float4*)(feat + i);
    uint2 o;
    o.x = pack_h2(fv.x, fv.y);
    o.y = pack_h2(fv.z, fv.w);
    *(uint2*)(g_a16 + i) = o;
}

// ---------------- prep: W1 [k][u] -> fp16 [u][k] ----------------
__global__ void prep_w1t_kernel(const float* __restrict__ W1) {
    int idx = blockIdx.x * 256 + threadIdx.x;   // 262144
    int k = idx & (DD - 1);
    int u = idx >> 9;
    g_w1t[(size_t)u * DD + k] = __float2half_rn(W1[(size_t)k * UU + u]);
}

// ---------------- comb[b][u] ----------------
__global__ void comb_kernel(const float* __restrict__ hidden,
                            const float* __restrict__ W2,
                            const float* __restrict__ W1b,
                            const float* __restrict__ W2b) {
    int b = blockIdx.x;
    int u = threadIdx.x;
    __shared__ float h[DD];
    h[u] = hidden[b * DD + u];
    __syncthreads();
    float acc = W1b[u] + W2b[u];
#pragma unroll 8
    for (int d = 0; d < DD; ++d)
        acc = fmaf(h[d], W2[d * UU + u], acc);
    g_comb[b * UU + u] = acc;
}

// ---------------- score GEMM: 4-stage cp.async pipeline, 2 CTAs/SM ----------------
// grid (2 nchunk, 32 ttile, 64 b), 256 threads = 8 warps (2 warpM x 4 warpN)
// CTA tile 64t x 256u x K=512; stage = one k16 slice (A 64x16, B 256x16 fp16, pitch 48B)
#define RPITCH 48
#define A_STAGE_B 3072            // 64 * 48
#define STAGE_B   15360           // A 3072 + B 12288
#define NSTAGE    4
#define SM_COMB   61440
#define SM_V      62464
#define SM_SROW   63488
#define SM_TOTAL  63744

__global__ void __launch_bounds__(256, 2)
score_kernel(const float* __restrict__ Vw) {
    extern __shared__ char smem[];
    uint32_t sb = smem_u32(smem);
    float* comb_s = (float*)(smem + SM_COMB);
    float* v_s    = (float*)(smem + SM_V);
    float* srow   = (float*)(smem + SM_SROW);

    int tid = threadIdx.x;
    int wid = tid >> 5, lane = tid & 31;
    int warpM = wid & 1, warpN = wid >> 1;
    int g = lane >> 2, tg = lane & 3;
    int grp = lane >> 3, r8 = lane & 7;

    int nchunk = blockIdx.x;
    int t0 = blockIdx.y << 6;
    int b = blockIdx.z;
    int u0 = nchunk << 8;

    comb_s[tid] = g_comb[b * UU + u0 + tid];
    v_s[tid] = Vw[u0 + tid];
    if (tid < 64) srow[tid] = 0.f;

    const __half* asrc = g_a16 + ((size_t)(b * TT + t0)) * DD;
    const __half* bsrc = g_w1t + (size_t)u0 * DD;

    // fill one k16 stage: A 128 xfers + B 512 xfers, 16B each
    auto fill = [&](int c, int s) {
        uint32_t base = sb + s * STAGE_B;
        int koff = c * 16;
#pragma unroll
        for (int i = 0; i < 3; ++i) {
            int idx = tid + 256 * i;
            if (idx < 128) {
                int r = idx >> 1, seg = idx & 1;
                cpa16(base + r * RPITCH + seg * 16,
                      asrc + (size_t)r * DD + koff + seg * 8);
            } else if (idx < 640) {
                int j = idx - 128;
                int r = j >> 1, seg = j & 1;
                cpa16(base + A_STAGE_B + r * RPITCH + seg * 16,
                      bsrc + (size_t)r * DD + koff + seg * 8);
            }
        }
    };

    // ldmatrix per-lane offsets (round-3 proven mappings), pitch 48B
    uint32_t rowA = (uint32_t)((r8 + 8 * (grp & 1)) * RPITCH + (grp >> 1) * 16);
    uint32_t rowB = (uint32_t)((r8 + 8 * (grp >> 1)) * RPITCH + (grp & 1) * 16);

    float acc[2][8][4];
#pragma unroll
    for (int i = 0; i < 2; ++i)
#pragma unroll
        for (int j = 0; j < 8; ++j)
#pragma unroll
            for (int q = 0; q < 4; ++q) acc[i][j][q] = 0.f;

    fill(0, 0); CP_COMMIT();
    fill(1, 1); CP_COMMIT();
    fill(2, 2); CP_COMMIT();

#pragma unroll 1
    for (int k16 = 0; k16 < 32; ++k16) {
        CP_WAIT(2);
        __syncthreads();
        if (k16 < 29) fill(k16 + 3, (k16 + 3) & 3);
        CP_COMMIT();

        uint32_t base = sb + (k16 & 3) * STAGE_B;
        uint32_t aBase = base + (warpM * 32) * RPITCH + rowA;
        uint32_t bBase = base + A_STAGE_B + (warpN * 64) * RPITCH + rowB;

        uint32_t a[2][4];
        LDSM4(a[0], aBase);
        LDSM4(a[1], aBase + 16 * RPITCH);
        uint32_t bb[4][4];
#pragma unroll
        for (int n4 = 0; n4 < 4; ++n4)
            LDSM4(bb[n4], bBase + n4 * (16 * RPITCH));

#pragma unroll
        for (int n4 = 0; n4 < 4; ++n4) {
            mma_f16(acc[0][2 * n4],     a[0], bb[n4][0], bb[n4][1]);
            mma_f16(acc[0][2 * n4 + 1], a[0], bb[n4][2], bb[n4][3]);
            mma_f16(acc[1][2 * n4],     a[1], bb[n4][0], bb[n4][1]);
            mma_f16(acc[1][2 * n4 + 1], a[1], bb[n4][2], bb[n4][3]);
        }
    }

    __syncthreads();

    // ---- epilogue: s = sum_u v[u] * tanh(acc + comb[u]) ----
#pragma unroll
    for (int mt = 0; mt < 2; ++mt) {
        float s0 = 0.f, s1 = 0.f;
#pragma unroll
        for (int nt = 0; nt < 8; ++nt) {
#pragma unroll
            for (int j = 0; j < 2; ++j) {
                int ul = warpN * 64 + nt * 8 + 2 * tg + j;
                float cb = comb_s[ul], vv = v_s[ul];
                s0 = fmaf(vv, tanhf(acc[mt][nt][j] + cb), s0);
                s1 = fmaf(vv, tanhf(acc[mt][nt][2 + j] + cb), s1);
            }
        }
        s0 += __shfl_xor_sync(0xffffffffu, s0, 1);
        s0 += __shfl_xor_sync(0xffffffffu, s0, 2);
        s1 += __shfl_xor_sync(0xffffffffu, s1, 1);
        s1 += __shfl_xor_sync(0xffffffffu, s1, 2);
        if (tg == 0) {
            int row = warpM * 32 + mt * 16 + g;
            atomicAdd(&srow[row], s0);
            atomicAdd(&srow[row + 8], s1);
        }
    }
    __syncthreads();
    if (tid < 64)
        g_spart[(size_t)nchunk * BB * TT + b * TT + t0 + tid] = srow[tid];
}

// ---------------- softmax stats + score combine ----------------
__global__ void stats_kernel() {
    int b = blockIdx.x;
    int tid = threadIdx.x;   // 256
    __shared__ float red[256];
    float m = -INFINITY;
    for (int t = tid; t < TT; t += 256) {
        float sc = g_spart[b * TT + t] + g_spart[BB * TT + b * TT + t];
        g_scores[b * TT + t] = sc;
        m = fmaxf(m, sc);
    }
    red[tid] = m;
    __syncthreads();
    for (int s = 128; s > 0; s >>= 1) {
        if (tid < s) red[tid] = fmaxf(red[tid], red[tid + s]);
        __syncthreads();
    }
    float mx = red[0];
    __syncthreads();
    float sm = 0.f;
    for (int t = tid; t < TT; t += 256)
        sm += expf(g_scores[b * TT + t] - mx);
    red[tid] = sm;
    __syncthreads();
    for (int s = 128; s > 0; s >>= 1) {
        if (tid < s) red[tid] += red[tid + s];
        __syncthreads();
    }
    if (tid == 0) { g_stats[b * 2] = mx; g_stats[b * 2 + 1] = red[0]; }
}

// ---------------- context partials (round-5 version) ----------------
__global__ void __launch_bounds__(512)
ctx_partial_kernel(const float* __restrict__ feat) {
    int b = blockIdx.x;
    int s = blockIdx.y;
    int tid = threadIdx.x;
    __shared__ float w[128];
    float mx = g_stats[b * 2], inv = 1.0f / g_stats[b * 2 + 1];
    int t0 = s * 128;
    if (tid < 128)
        w[tid] = expf(g_scores[b * TT + t0 + tid] - mx) * inv;
    __syncthreads();
    int tl = tid >> 7;
    int dq = (tid & 127) << 2;
    float4 acc = make_float4(0.f, 0.f, 0.f, 0.f);
    const float* fb = feat + ((size_t)b * TT + t0) * DD;
#pragma unroll 4
    for (int i = 0; i < 32; ++i) {
        int t = tl + (i << 2);
        float4 f = *(const float4*)(fb + (size_t)t * DD + dq);
        float ww = w[t];
        acc.x = fmaf(ww, f.x, acc.x);
        acc.y = fmaf(ww, f.y, acc.y);
        acc.z = fmaf(ww, f.z, acc.z);
        acc.w = fmaf(ww, f.w, acc.w);
    }
    *(float4*)(&g_partial[((((size_t)b * 16 + s) * 4) + tl) * DD + dq]) = acc;
}

__global__ void ctx_reduce_kernel(float* __restrict__ out) {
    int b = blockIdx.x;
    int d = threadIdx.x;
    float a = 0.f;
#pragma unroll
    for (int s = 0; s < 64; ++s)
        a += g_partial[((size_t)b * 64 + s) * DD + d];
    out[b * DD + d] = a;
}

// ---------------- launch ----------------
extern "C" void kernel_launch(void* const* d_in, const int* in_sizes, int n_in,
                              void* d_out, int out_size) {
    const float* features = (const float*)d_in[0];
    const float* hidden   = (const float*)d_in[1];
    const float* W1_w     = (const float*)d_in[2];
    const float* W1_b     = (const float*)d_in[3];
    const float* W2_w     = (const float*)d_in[4];
    const float* W2_b     = (const float*)d_in[5];
    const float* V_w      = (const float*)d_in[6];
    // V_b: constant shift, softmax-invariant -> dropped
    float* out = (float*)d_out;

    cudaFuncSetAttribute(score_kernel, cudaFuncAttributeMaxDynamicSharedMemorySize, SM_TOTAL);

    prep_a16_kernel<<<(int)((size_t)BB * TT * DD / 4 / 256), 256>>>(features);
    prep_w1t_kernel<<<UU * DD / 256, 256>>>(W1_w);
    comb_kernel<<<BB, UU>>>(hidden, W2_w, W1_b, W2_b);

    dim3 sgrid(2, 32, BB);
    score_kernel<<<sgrid, 256, SM_TOTAL>>>(V_w);

    stats_kernel<<<BB, 256>>>();
    dim3 cgrid(BB, 16);
    ctx_partial_kernel<<<cgrid, 512>>>(features);
    ctx_reduce_kernel<<<BB, DD>>>(out);
}

// round 11
// speedup vs baseline: 1.2536x; 1.2536x over previous
#include <cuda_runtime.h>
#include <cuda_fp16.h>
#include <math.h>
#include <stdint.h>

#define BB 64
#define TT 2048
#define DD 512
#define UU 512

// ---------------- device scratch ----------------
__device__ float g_comb[BB * UU];
__device__ float g_scores[BB * TT];
__device__ float g_spart[2 * BB * TT];
__device__ float g_stats[BB * 2];
// A fragments: [b][t16 0..127][k16 0..31][lane 0..31] -> uint4 (a0,a1,a2,a3) fp16x2
__device__ uint4 g_afrag[BB * 128 * 32 * 32];
// B fragments (fp16, 2 n8 per uint4): [n4 0..31][k16 0..31][lane 0..31]
__device__ uint4 g_bfrag[32 * 32 * 32];

// ---------------- helpers ----------------
__device__ __forceinline__ uint32_t pack_h2(float x, float y) {
    __half2 h = __floats2half2_rn(x, y);
    return *(uint32_t*)&h;
}

__device__ __forceinline__ void mma_f16(float* d, const uint4& a, uint32_t b0, uint32_t b1) {
    asm volatile(
        "mma.sync.aligned.m16n8k16.row.col.f32.f16.f16.f32 "
        "{%0,%1,%2,%3}, {%4,%5,%6,%7}, {%8,%9}, {%0,%1,%2,%3};"
        : "+f"(d[0]), "+f"(d[1]), "+f"(d[2]), "+f"(d[3])
        : "r"(a.x), "r"(a.y), "r"(a.z), "r"(a.w), "r"(b0), "r"(b1));
}

// ---------------- prep: features fp32 -> fp16 fragment-major ----------------
__global__ void prep_afrag_kernel(const float* __restrict__ feat) {
    int gidx = blockIdx.x * 256 + threadIdx.x;      // 8388608
    int lane = gidx & 31;
    int k16 = (gidx >> 5) & 31;
    int t16 = (gidx >> 10) & 127;
    int b = gidx >> 17;
    int g = lane >> 2, tg = lane & 3;
    int tA = t16 * 16 + g;
    int kA = k16 * 16 + 2 * tg;
    const float* base = feat + ((size_t)b * TT) * DD;
    float2 f00 = *(const float2*)(base + (size_t)tA * DD + kA);
    float2 f10 = *(const float2*)(base + (size_t)(tA + 8) * DD + kA);
    float2 f01 = *(const float2*)(base + (size_t)tA * DD + kA + 8);
    float2 f11 = *(const float2*)(base + (size_t)(tA + 8) * DD + kA + 8);
    uint4 o;
    o.x = pack_h2(f00.x, f00.y);
    o.y = pack_h2(f10.x, f10.y);
    o.z = pack_h2(f01.x, f01.y);
    o.w = pack_h2(f11.x, f11.y);
    g_afrag[gidx] = o;
}

// ---------------- prep: W1 -> fp16 fragment-major (2 n8 per uint4) ----------------
__global__ void prep_bfrag_kernel(const float* __restrict__ W1) {
    int gidx = blockIdx.x * 256 + threadIdx.x;      // 32768
    int lane = gidx & 31;
    int k16 = (gidx >> 5) & 31;
    int n4 = gidx >> 10;
    int g = lane >> 2, tg = lane & 3;
    int k = k16 * 16 + 2 * tg;
    int ua = (2 * n4) * 8 + g;
    int ub = (2 * n4 + 1) * 8 + g;
    uint4 o;
    o.x = pack_h2(W1[(size_t)k * UU + ua],       W1[(size_t)(k + 1) * UU + ua]);
    o.y = pack_h2(W1[(size_t)(k + 8) * UU + ua], W1[(size_t)(k + 9) * UU + ua]);
    o.z = pack_h2(W1[(size_t)k * UU + ub],       W1[(size_t)(k + 1) * UU + ub]);
    o.w = pack_h2(W1[(size_t)(k + 8) * UU + ub], W1[(size_t)(k + 9) * UU + ub]);
    g_bfrag[gidx] = o;
}

// ---------------- comb[b][u] ----------------
__global__ void comb_kernel(const float* __restrict__ hidden,
                            const float* __restrict__ W2,
                            const float* __restrict__ W1b,
                            const float* __restrict__ W2b) {
    int b = blockIdx.x;
    int u = threadIdx.x;
    __shared__ float h[DD];
    h[u] = hidden[b * DD + u];
    __syncthreads();
    float acc = W1b[u] + W2b[u];
#pragma unroll 8
    for (int d = 0; d < DD; ++d)
        acc = fmaf(h[d], W2[d * UU + u], acc);
    g_comb[b * UU + u] = acc;
}

// ---------------- score GEMM: round-5 winner (byte-identical) ----------------
__global__ void __launch_bounds__(512)
score_kernel(const float* __restrict__ Vw) {
    __shared__ float comb_s[256];
    __shared__ float v_s[256];
    __shared__ float srow[128];

    int tid = threadIdx.x;
    int wid = tid >> 5, lane = tid & 31;
    int warpM = wid & 3, warpN = wid >> 2;
    int g = lane >> 2, tg = lane & 3;

    int nchunk = blockIdx.x;
    int t0 = blockIdx.y << 7;
    int b = blockIdx.z;
    int u0 = nchunk << 8;

    if (tid < 256) {
        comb_s[tid] = g_comb[b * UU + u0 + tid];
        v_s[tid] = Vw[u0 + tid];
    }
    if (tid < 128) srow[tid] = 0.f;

    int tt0 = (t0 >> 4) + warpM * 2;
    const uint4* pA0 = g_afrag + (((size_t)(b * 128 + tt0) * 32) * 32 + lane);
    const uint4* pA1 = pA0 + 32 * 32;
    const uint4* pB  = g_bfrag + (((size_t)(nchunk * 16 + warpN * 4) * 32) * 32 + lane);

    float acc[2][8][4];
#pragma unroll
    for (int i = 0; i < 2; ++i)
#pragma unroll
        for (int j = 0; j < 8; ++j)
#pragma unroll
            for (int q = 0; q < 4; ++q) acc[i][j][q] = 0.f;

    uint4 Ab[2][2], Bb[2][4];
    Ab[0][0] = pA0[0];
    Ab[0][1] = pA1[0];
#pragma unroll
    for (int j = 0; j < 4; ++j) Bb[0][j] = pB[j * 1024];

#pragma unroll 2
    for (int k16 = 0; k16 < 32; ++k16) {
        int cur = k16 & 1, nxt = cur ^ 1;
        if (k16 < 31) {
            int off = (k16 + 1) * 32;
            Ab[nxt][0] = pA0[off];
            Ab[nxt][1] = pA1[off];
#pragma unroll
            for (int j = 0; j < 4; ++j) Bb[nxt][j] = pB[j * 1024 + off];
        }
#pragma unroll
        for (int n4 = 0; n4 < 4; ++n4) {
            uint4 B4 = Bb[cur][n4];
            mma_f16(acc[0][2 * n4],     Ab[cur][0], B4.x, B4.y);
            mma_f16(acc[0][2 * n4 + 1], Ab[cur][0], B4.z, B4.w);
            mma_f16(acc[1][2 * n4],     Ab[cur][1], B4.x, B4.y);
            mma_f16(acc[1][2 * n4 + 1], Ab[cur][1], B4.z, B4.w);
        }
    }

    __syncthreads();

    float s[4] = {0.f, 0.f, 0.f, 0.f};
#pragma unroll
    for (int nt = 0; nt < 8; ++nt) {
#pragma unroll
        for (int j = 0; j < 2; ++j) {
            int ul = warpN * 64 + nt * 8 + 2 * tg + j;
            float cb = comb_s[ul], vv = v_s[ul];
            s[0] = fmaf(vv, tanhf(acc[0][nt][j] + cb), s[0]);
            s[1] = fmaf(vv, tanhf(acc[0][nt][2 + j] + cb), s[1]);
            s[2] = fmaf(vv, tanhf(acc[1][nt][j] + cb), s[2]);
            s[3] = fmaf(vv, tanhf(acc[1][nt][2 + j] + cb), s[3]);
        }
    }
#pragma unroll
    for (int i = 0; i < 4; ++i) {
        s[i] += __shfl_xor_sync(0xffffffffu, s[i], 1);
        s[i] += __shfl_xor_sync(0xffffffffu, s[i], 2);
    }
    if (tg == 0) {
        int rbase = warpM * 32;
        atomicAdd(&srow[rbase + g], s[0]);
        atomicAdd(&srow[rbase + g + 8], s[1]);
        atomicAdd(&srow[rbase + 16 + g], s[2]);
        atomicAdd(&srow[rbase + 16 + g + 8], s[3]);
    }
    __syncthreads();
    if (tid < 128)
        g_spart[(size_t)nchunk * BB * TT + b * TT + t0 + tid] = srow[tid];
}

// ---------------- softmax stats + score combine ----------------
__global__ void stats_kernel() {
    int b = blockIdx.x;
    int tid = threadIdx.x;   // 256
    __shared__ float red[256];
    float m = -INFINITY;
    for (int t = tid; t < TT; t += 256) {
        float sc = g_spart[b * TT + t] + g_spart[BB * TT + b * TT + t];
        g_scores[b * TT + t] = sc;
        m = fmaxf(m, sc);
    }
    red[tid] = m;
    __syncthreads();
    for (int s = 128; s > 0; s >>= 1) {
        if (tid < s) red[tid] = fmaxf(red[tid], red[tid + s]);
        __syncthreads();
    }
    float mx = red[0];
    __syncthreads();
    float sm = 0.f;
    for (int t = tid; t < TT; t += 256)
        sm += expf(g_scores[b * TT + t] - mx);
    red[tid] = sm;
    __syncthreads();
    for (int s = 128; s > 0; s >>= 1) {
        if (tid < s) red[tid] += red[tid + s];
        __syncthreads();
    }
    if (tid == 0) { g_stats[b * 2] = mx; g_stats[b * 2 + 1] = red[0]; }
}

// ---------------- context: read fp16 fragments, write final output ----------------
// grid (64 b, 4 kgroup), 256 threads = 8 warps; warp w -> k16 = kgroup*8 + w
// Each warp streams all 128 t16 tiles of its (b, k16) slice: one coalesced
// LDG.128 per tile; lane accumulates 4 d-positions; 3 shfl rounds reduce over g.
__global__ void __launch_bounds__(256)
ctx_kernel(float* __restrict__ out) {
    int b = blockIdx.x;
    int kg = blockIdx.y;
    int tid = threadIdx.x;
    int wid = tid >> 5, lane = tid & 31;
    int g = lane >> 2, tg = lane & 3;
    int k16 = kg * 8 + wid;

    __shared__ float w[TT];
    float mx = g_stats[b * 2], inv = 1.0f / g_stats[b * 2 + 1];
    for (int t = tid; t < TT; t += 256)
        w[t] = expf(g_scores[b * TT + t] - mx) * inv;
    __syncthreads();

    const uint4* pA = g_afrag + (((size_t)(b * 128) * 32 + k16) * 32 + lane);
    float a0 = 0.f, a1 = 0.f, a2 = 0.f, a3 = 0.f;
#pragma unroll 4
    for (int t16 = 0; t16 < 128; ++t16) {
        uint4 v = pA[(size_t)t16 * 1024];
        float wlo = w[t16 * 16 + g];
        float whi = w[t16 * 16 + 8 + g];
        float2 f;
        f = __half22float2(*(__half2*)&v.x);
        a0 = fmaf(wlo, f.x, a0); a1 = fmaf(wlo, f.y, a1);
        f = __half22float2(*(__half2*)&v.y);
        a0 = fmaf(whi, f.x, a0); a1 = fmaf(whi, f.y, a1);
        f = __half22float2(*(__half2*)&v.z);
        a2 = fmaf(wlo, f.x, a2); a3 = fmaf(wlo, f.y, a3);
        f = __half22float2(*(__half2*)&v.w);
        a2 = fmaf(whi, f.x, a2); a3 = fmaf(whi, f.y, a3);
    }
#pragma unroll
    for (int o = 4; o <= 16; o <<= 1) {
        a0 += __shfl_xor_sync(0xffffffffu, a0, o);
        a1 += __shfl_xor_sync(0xffffffffu, a1, o);
        a2 += __shfl_xor_sync(0xffffffffu, a2, o);
        a3 += __shfl_xor_sync(0xffffffffu, a3, o);
    }
    if (g == 0) {
        int d = k16 * 16 + 2 * tg;
        out[b * DD + d]     = a0;
        out[b * DD + d + 1] = a1;
        out[b * DD + d + 8] = a2;
        out[b * DD + d + 9] = a3;
    }
}

// ---------------- launch ----------------
extern "C" void kernel_launch(void* const* d_in, const int* in_sizes, int n_in,
                              void* d_out, int out_size) {
    const float* features = (const float*)d_in[0];
    const float* hidden   = (const float*)d_in[1];
    const float* W1_w     = (const float*)d_in[2];
    const float* W1_b     = (const float*)d_in[3];
    const float* W2_w     = (const float*)d_in[4];
    const float* W2_b     = (const float*)d_in[5];
    const float* V_w      = (const float*)d_in[6];
    // V_b: constant shift, softmax-invariant -> dropped
    float* out = (float*)d_out;

    prep_afrag_kernel<<<BB * 128 * 32 * 32 / 256, 256>>>(features);
    prep_bfrag_kernel<<<32 * 32 * 32 / 256, 256>>>(W1_w);
    comb_kernel<<<BB, UU>>>(hidden, W2_w, W1_b, W2_b);

    dim3 sgrid(2, 16, BB);
    score_kernel<<<sgrid, 512>>>(V_w);

    stats_kernel<<<BB, 256>>>();

    dim3 cgrid(BB, 4);
    ctx_kernel<<<cgrid, 256>>>(out);
}

// round 12
// speedup vs baseline: 1.3595x; 1.0845x over previous
#include <cuda_runtime.h>
#include <cuda_fp16.h>
#include <math.h>
#include <stdint.h>

#define BB 64
#define TT 2048
#define DD 512
#define UU 512

// ---------------- device scratch ----------------
__device__ float g_comb[BB * UU];
__device__ float g_spart[2 * BB * TT];
// A fragments: [b][t16 0..127][k16 0..31][lane 0..31] -> uint4 (a0,a1,a2,a3) fp16x2
__device__ uint4 g_afrag[BB * 128 * 32 * 32];
// B fragments (fp16, 2 n8 per uint4): [n4 0..31][k16 0..31][lane 0..31]
__device__ uint4 g_bfrag[32 * 32 * 32];

// ---------------- helpers ----------------
__device__ __forceinline__ uint32_t pack_h2(float x, float y) {
    __half2 h = __floats2half2_rn(x, y);
    return *(uint32_t*)&h;
}

__device__ __forceinline__ float tanh_fast(float x) {
    float y;
    asm("tanh.approx.f32 %0, %1;" : "=f"(y) : "f"(x));
    return y;
}

__device__ __forceinline__ void mma_f16(float* d, const uint4& a, uint32_t b0, uint32_t b1) {
    asm volatile(
        "mma.sync.aligned.m16n8k16.row.col.f32.f16.f16.f32 "
        "{%0,%1,%2,%3}, {%4,%5,%6,%7}, {%8,%9}, {%0,%1,%2,%3};"
        : "+f"(d[0]), "+f"(d[1]), "+f"(d[2]), "+f"(d[3])
        : "r"(a.x), "r"(a.y), "r"(a.z), "r"(a.w), "r"(b0), "r"(b1));
}

// ---------------- prep: features fp32 -> fp16 fragment-major ----------------
__global__ void prep_afrag_kernel(const float* __restrict__ feat) {
    int gidx = blockIdx.x * 256 + threadIdx.x;      // 8388608
    int lane = gidx & 31;
    int k16 = (gidx >> 5) & 31;
    int t16 = (gidx >> 10) & 127;
    int b = gidx >> 17;
    int g = lane >> 2, tg = lane & 3;
    int tA = t16 * 16 + g;
    int kA = k16 * 16 + 2 * tg;
    const float* base = feat + ((size_t)b * TT) * DD;
    float2 f00 = *(const float2*)(base + (size_t)tA * DD + kA);
    float2 f10 = *(const float2*)(base + (size_t)(tA + 8) * DD + kA);
    float2 f01 = *(const float2*)(base + (size_t)tA * DD + kA + 8);
    float2 f11 = *(const float2*)(base + (size_t)(tA + 8) * DD + kA + 8);
    uint4 o;
    o.x = pack_h2(f00.x, f00.y);
    o.y = pack_h2(f10.x, f10.y);
    o.z = pack_h2(f01.x, f01.y);
    o.w = pack_h2(f11.x, f11.y);
    g_afrag[gidx] = o;
}

// ---------------- prep: W1 -> fp16 fragment-major (2 n8 per uint4) ----------------
__global__ void prep_bfrag_kernel(const float* __restrict__ W1) {
    int gidx = blockIdx.x * 256 + threadIdx.x;      // 32768
    int lane = gidx & 31;
    int k16 = (gidx >> 5) & 31;
    int n4 = gidx >> 10;
    int g = lane >> 2, tg = lane & 3;
    int k = k16 * 16 + 2 * tg;
    int ua = (2 * n4) * 8 + g;
    int ub = (2 * n4 + 1) * 8 + g;
    uint4 o;
    o.x = pack_h2(W1[(size_t)k * UU + ua],       W1[(size_t)(k + 1) * UU + ua]);
    o.y = pack_h2(W1[(size_t)(k + 8) * UU + ua], W1[(size_t)(k + 9) * UU + ua]);
    o.z = pack_h2(W1[(size_t)k * UU + ub],       W1[(size_t)(k + 1) * UU + ub]);
    o.w = pack_h2(W1[(size_t)(k + 8) * UU + ub], W1[(size_t)(k + 9) * UU + ub]);
    g_bfrag[gidx] = o;
}

// ---------------- comb[b][u] ----------------
__global__ void comb_kernel(const float* __restrict__ hidden,
                            const float* __restrict__ W2,
                            const float* __restrict__ W1b,
                            const float* __restrict__ W2b) {
    int b = blockIdx.x;
    int u = threadIdx.x;
    __shared__ float h[DD];
    h[u] = hidden[b * DD + u];
    __syncthreads();
    float acc = W1b[u] + W2b[u];
#pragma unroll 8
    for (int d = 0; d < DD; ++d)
        acc = fmaf(h[d], W2[d * UU + u], acc);
    g_comb[b * UU + u] = acc;
}

// ---------------- score GEMM: round-5 mainloop + fast-tanh epilogue ----------------
__global__ void __launch_bounds__(512)
score_kernel(const float* __restrict__ Vw) {
    __shared__ float comb_s[256];
    __shared__ float v_s[256];
    __shared__ float srow[128];

    int tid = threadIdx.x;
    int wid = tid >> 5, lane = tid & 31;
    int warpM = wid & 3, warpN = wid >> 2;
    int g = lane >> 2, tg = lane & 3;

    int nchunk = blockIdx.x;
    int t0 = blockIdx.y << 7;
    int b = blockIdx.z;
    int u0 = nchunk << 8;

    if (tid < 256) {
        comb_s[tid] = g_comb[b * UU + u0 + tid];
        v_s[tid] = Vw[u0 + tid];
    }
    if (tid < 128) srow[tid] = 0.f;

    int tt0 = (t0 >> 4) + warpM * 2;
    const uint4* pA0 = g_afrag + (((size_t)(b * 128 + tt0) * 32) * 32 + lane);
    const uint4* pA1 = pA0 + 32 * 32;
    const uint4* pB  = g_bfrag + (((size_t)(nchunk * 16 + warpN * 4) * 32) * 32 + lane);

    float acc[2][8][4];
#pragma unroll
    for (int i = 0; i < 2; ++i)
#pragma unroll
        for (int j = 0; j < 8; ++j)
#pragma unroll
            for (int q = 0; q < 4; ++q) acc[i][j][q] = 0.f;

    uint4 Ab[2][2], Bb[2][4];
    Ab[0][0] = pA0[0];
    Ab[0][1] = pA1[0];
#pragma unroll
    for (int j = 0; j < 4; ++j) Bb[0][j] = pB[j * 1024];

#pragma unroll 2
    for (int k16 = 0; k16 < 32; ++k16) {
        int cur = k16 & 1, nxt = cur ^ 1;
        if (k16 < 31) {
            int off = (k16 + 1) * 32;
            Ab[nxt][0] = pA0[off];
            Ab[nxt][1] = pA1[off];
#pragma unroll
            for (int j = 0; j < 4; ++j) Bb[nxt][j] = pB[j * 1024 + off];
        }
#pragma unroll
        for (int n4 = 0; n4 < 4; ++n4) {
            uint4 B4 = Bb[cur][n4];
            mma_f16(acc[0][2 * n4],     Ab[cur][0], B4.x, B4.y);
            mma_f16(acc[0][2 * n4 + 1], Ab[cur][0], B4.z, B4.w);
            mma_f16(acc[1][2 * n4],     Ab[cur][1], B4.x, B4.y);
            mma_f16(acc[1][2 * n4 + 1], Ab[cur][1], B4.z, B4.w);
        }
    }

    __syncthreads();

    float s[4] = {0.f, 0.f, 0.f, 0.f};
#pragma unroll
    for (int nt = 0; nt < 8; ++nt) {
#pragma unroll
        for (int j = 0; j < 2; ++j) {
            int ul = warpN * 64 + nt * 8 + 2 * tg + j;
            float cb = comb_s[ul], vv = v_s[ul];
            s[0] = fmaf(vv, tanh_fast(acc[0][nt][j] + cb), s[0]);
            s[1] = fmaf(vv, tanh_fast(acc[0][nt][2 + j] + cb), s[1]);
            s[2] = fmaf(vv, tanh_fast(acc[1][nt][j] + cb), s[2]);
            s[3] = fmaf(vv, tanh_fast(acc[1][nt][2 + j] + cb), s[3]);
        }
    }
#pragma unroll
    for (int i = 0; i < 4; ++i) {
        s[i] += __shfl_xor_sync(0xffffffffu, s[i], 1);
        s[i] += __shfl_xor_sync(0xffffffffu, s[i], 2);
    }
    if (tg == 0) {
        int rbase = warpM * 32;
        atomicAdd(&srow[rbase + g], s[0]);
        atomicAdd(&srow[rbase + g + 8], s[1]);
        atomicAdd(&srow[rbase + 16 + g], s[2]);
        atomicAdd(&srow[rbase + 16 + g + 8], s[3]);
    }
    __syncthreads();
    if (tid < 128)
        g_spart[(size_t)nchunk * BB * TT + b * TT + t0 + tid] = srow[tid];
}

// ---------------- context: inline softmax stats + fp16-fragment reduction ----------------
// grid (64 b, 4 kgroup), 256 threads = 8 warps; warp w -> k16 = kgroup*8 + w
__global__ void __launch_bounds__(256)
ctx_kernel(float* __restrict__ out) {
    int b = blockIdx.x;
    int kg = blockIdx.y;
    int tid = threadIdx.x;
    int wid = tid >> 5, lane = tid & 31;
    int g = lane >> 2, tg = lane & 3;
    int k16 = kg * 8 + wid;

    __shared__ float w[TT];
    __shared__ float red[256];

    // combine score partials + block-wide max
    float m = -INFINITY;
    for (int t = tid; t < TT; t += 256) {
        float sc = g_spart[b * TT + t] + g_spart[BB * TT + b * TT + t];
        w[t] = sc;
        m = fmaxf(m, sc);
    }
    red[tid] = m;
    __syncthreads();
    for (int s = 128; s > 0; s >>= 1) {
        if (tid < s) red[tid] = fmaxf(red[tid], red[tid + s]);
        __syncthreads();
    }
    float mx = red[0];
    __syncthreads();
    // sumexp
    float sm = 0.f;
    for (int t = tid; t < TT; t += 256)
        sm += expf(w[t] - mx);
    red[tid] = sm;
    __syncthreads();
    for (int s = 128; s > 0; s >>= 1) {
        if (tid < s) red[tid] += red[tid + s];
        __syncthreads();
    }
    float inv = 1.0f / red[0];
    __syncthreads();
    for (int t = tid; t < TT; t += 256)
        w[t] = expf(w[t] - mx) * inv;
    __syncthreads();

    const uint4* pA = g_afrag + (((size_t)(b * 128) * 32 + k16) * 32 + lane);
    float a0 = 0.f, a1 = 0.f, a2 = 0.f, a3 = 0.f;
#pragma unroll 4
    for (int t16 = 0; t16 < 128; ++t16) {
        uint4 v = pA[(size_t)t16 * 1024];
        float wlo = w[t16 * 16 + g];
        float whi = w[t16 * 16 + 8 + g];
        float2 f;
        f = __half22float2(*(__half2*)&v.x);
        a0 = fmaf(wlo, f.x, a0); a1 = fmaf(wlo, f.y, a1);
        f = __half22float2(*(__half2*)&v.y);
        a0 = fmaf(whi, f.x, a0); a1 = fmaf(whi, f.y, a1);
        f = __half22float2(*(__half2*)&v.z);
        a2 = fmaf(wlo, f.x, a2); a3 = fmaf(wlo, f.y, a3);
        f = __half22float2(*(__half2*)&v.w);
        a2 = fmaf(whi, f.x, a2); a3 = fmaf(whi, f.y, a3);
    }
#pragma unroll
    for (int o = 4; o <= 16; o <<= 1) {
        a0 += __shfl_xor_sync(0xffffffffu, a0, o);
        a1 += __shfl_xor_sync(0xffffffffu, a1, o);
        a2 += __shfl_xor_sync(0xffffffffu, a2, o);
        a3 += __shfl_xor_sync(0xffffffffu, a3, o);
    }
    if (g == 0) {
        int d = k16 * 16 + 2 * tg;
        out[b * DD + d]     = a0;
        out[b * DD + d + 1] = a1;
        out[b * DD + d + 8] = a2;
        out[b * DD + d + 9] = a3;
    }
}

// ---------------- launch ----------------
extern "C" void kernel_launch(void* const* d_in, const int* in_sizes, int n_in,
                              void* d_out, int out_size) {
    const float* features = (const float*)d_in[0];
    const float* hidden   = (const float*)d_in[1];
    const float* W1_w     = (const float*)d_in[2];
    const float* W1_b     = (const float*)d_in[3];
    const float* W2_w     = (const float*)d_in[4];
    const float* W2_b     = (const float*)d_in[5];
    const float* V_w      = (const float*)d_in[6];
    // V_b: constant shift, softmax-invariant -> dropped
    float* out = (float*)d_out;

    prep_afrag_kernel<<<BB * 128 * 32 * 32 / 256, 256>>>(features);
    prep_bfrag_kernel<<<32 * 32 * 32 / 256, 256>>>(W1_w);
    comb_kernel<<<BB, UU>>>(hidden, W2_w, W1_b, W2_b);

    dim3 sgrid(2, 16, BB);
    score_kernel<<<sgrid, 512>>>(V_w);

    dim3 cgrid(BB, 4);
    ctx_kernel<<<cgrid, 256>>>(out);
}